// round 1
// baseline (speedup 1.0000x reference)
#include <cuda_runtime.h>

#define BATCH 8
#define NSEQ 1024
#define DIM 768
#define NH 16
#define HD 48
#define SCALE 0.14433756729740643f  /* 48^-0.5 */

// ---------------- scratch (static __device__, allocation-guard safe) ----------
__device__ float g_q[BATCH * NH * NSEQ * HD];   // [b][h][n][d], pre-scaled
__device__ float g_k[BATCH * NH * NSEQ * HD];
__device__ float g_v[BATCH * NH * NSEQ * HD];
__device__ float g_S[(size_t)BATCH * NH * NSEQ * NSEQ];  // 512MB logits; reused in-place for post-mix probs
__device__ float g_O[BATCH * NSEQ * DIM];       // attn output pre-proj, [b][n][h*HD+d]

// ---------------- K1 / K5: classic 128x128x8 SGEMM, C = A @ W^T + bias -------
// A: [M,K] row-major. W: [Nc,K] row-major (so W^T access = dot of K-major rows).
// MODE 0: QKV epilogue (scatter into g_q/g_k/g_v, scale q). MODE 1: plain C+bias.
template <int MODE>
__global__ __launch_bounds__(256) void gemm128(
    const float* __restrict__ A, const float* __restrict__ W,
    const float* __restrict__ bias, float* __restrict__ C, int K, int Nc) {
    __shared__ float As[8][128];
    __shared__ float Bs[8][128];

    const int tid = threadIdx.x;
    const int brow = blockIdx.y;   // M tile
    const int bcol = blockIdx.x;   // N tile

    const float* Ap = (MODE == 1) ? g_O : A;

    const int a_r = tid >> 1;
    const int a_c = (tid & 1) * 4;
    const float* Ag = Ap + (size_t)(brow * 128 + a_r) * K + a_c;
    const float* Wg = W + (size_t)(bcol * 128 + a_r) * K + a_c;

    const int ty = tid >> 4;   // 0..15 -> row group of 8
    const int tx = tid & 15;   // 0..15 -> col group of 8

    float acc[8][8];
#pragma unroll
    for (int i = 0; i < 8; i++)
#pragma unroll
        for (int j = 0; j < 8; j++) acc[i][j] = 0.f;

    for (int kt = 0; kt < K; kt += 8) {
        float4 av = *(const float4*)(Ag + kt);
        float4 wv = *(const float4*)(Wg + kt);
        As[a_c + 0][a_r] = av.x; As[a_c + 1][a_r] = av.y;
        As[a_c + 2][a_r] = av.z; As[a_c + 3][a_r] = av.w;
        Bs[a_c + 0][a_r] = wv.x; Bs[a_c + 1][a_r] = wv.y;
        Bs[a_c + 2][a_r] = wv.z; Bs[a_c + 3][a_r] = wv.w;
        __syncthreads();
#pragma unroll
        for (int kk = 0; kk < 8; kk++) {
            float af[8], bf[8];
#pragma unroll
            for (int i = 0; i < 8; i++) af[i] = As[kk][ty * 8 + i];
#pragma unroll
            for (int j = 0; j < 8; j++) bf[j] = Bs[kk][tx * 8 + j];
#pragma unroll
            for (int i = 0; i < 8; i++)
#pragma unroll
                for (int j = 0; j < 8; j++) acc[i][j] += af[i] * bf[j];
        }
        __syncthreads();
    }

#pragma unroll
    for (int i = 0; i < 8; i++) {
        const int m = brow * 128 + ty * 8 + i;
#pragma unroll
        for (int j = 0; j < 8; j++) {
            const int c = bcol * 128 + tx * 8 + j;
            float v = acc[i][j] + bias[c];
            if (MODE == 0) {
                const int b = m >> 10, n = m & 1023;
                const int t = c / DIM;
                const int r = c - t * DIM;
                const int h = r / HD, d = r - h * HD;
                const int idx = (((b * NH + h) * NSEQ) + n) * HD + d;
                if (t == 0)      g_q[idx] = v * SCALE;
                else if (t == 1) g_k[idx] = v;
                else             g_v[idx] = v;
            } else {
                C[(size_t)m * Nc + c] = v;
            }
        }
    }
}

// ---------------- K2: S = q @ k^T per (b,h); 64x64 tile, K=48 resident -------
__global__ __launch_bounds__(256) void qk_kernel() {
    __shared__ float Qs[64][HD + 1];
    __shared__ float Ks[64][HD + 1];
    const int bh = blockIdx.z;
    const int tid = threadIdx.x;
    const float* qb = g_q + (size_t)bh * NSEQ * HD + blockIdx.y * 64 * HD;
    const float* kb = g_k + (size_t)bh * NSEQ * HD + blockIdx.x * 64 * HD;
    for (int i = tid; i < 64 * HD; i += 256) {
        Qs[i / HD][i % HD] = qb[i];
        Ks[i / HD][i % HD] = kb[i];
    }
    __syncthreads();
    const int tx = tid & 15, ty = tid >> 4;
    float acc[4][4];
#pragma unroll
    for (int i = 0; i < 4; i++)
#pragma unroll
        for (int j = 0; j < 4; j++) acc[i][j] = 0.f;
#pragma unroll 8
    for (int d = 0; d < HD; d++) {
        float qf[4], kf[4];
#pragma unroll
        for (int i = 0; i < 4; i++) qf[i] = Qs[ty * 4 + i][d];
#pragma unroll
        for (int j = 0; j < 4; j++) kf[j] = Ks[tx * 4 + j][d];
#pragma unroll
        for (int i = 0; i < 4; i++)
#pragma unroll
            for (int j = 0; j < 4; j++) acc[i][j] += qf[i] * kf[j];
    }
    float* Sg = g_S + (size_t)bh * NSEQ * NSEQ;
#pragma unroll
    for (int i = 0; i < 4; i++)
#pragma unroll
        for (int j = 0; j < 4; j++)
            Sg[(size_t)(blockIdx.y * 64 + ty * 4 + i) * NSEQ + blockIdx.x * 64 + tx * 4 + j] = acc[i][j];
}

// ---------------- K3: fused mix1 -> softmax -> mix2, in place on g_S ---------
// one block per (b,q): loads S[b,:,q,:] (16x1024 = 64KB) into dynamic smem.
__global__ __launch_bounds__(256) void mix_softmax_kernel(
    const float* __restrict__ wl, const float* __restrict__ bl,
    const float* __restrict__ ww, const float* __restrict__ bw) {
    extern __shared__ float s[];  // [16][1024]
    __shared__ float wls[256], wws[256], bls[16], bws[16];

    const int tid = threadIdx.x;
    const int bq = blockIdx.x;
    const int b = bq >> 10, q = bq & 1023;

    wls[tid] = wl[tid];
    wws[tid] = ww[tid];
    if (tid < 16) { bls[tid] = bl[tid]; bws[tid] = bw[tid]; }

    const size_t rowbase = (size_t)(b * NH) * NSEQ * NSEQ + (size_t)q * NSEQ;
#pragma unroll
    for (int h = 0; h < NH; h++) {
        const float* src = g_S + rowbase + (size_t)h * NSEQ * NSEQ;
        for (int k = tid; k < NSEQ; k += 256) s[h * NSEQ + k] = src[k];
    }
    __syncthreads();

    // mix1 column-wise, in place
    for (int k = tid; k < NSEQ; k += 256) {
        float sv[NH], mv[NH];
#pragma unroll
        for (int h = 0; h < NH; h++) sv[h] = s[h * NSEQ + k];
#pragma unroll
        for (int g = 0; g < NH; g++) {
            float t = bls[g];
#pragma unroll
            for (int h = 0; h < NH; h++) t += wls[g * NH + h] * sv[h];
            mv[g] = t;
        }
#pragma unroll
        for (int g = 0; g < NH; g++) s[g * NSEQ + k] = mv[g];
    }
    __syncthreads();

    // softmax per head row (warp w handles rows w and w+8)
    const int lane = tid & 31, warp = tid >> 5;
    for (int g = warp; g < NH; g += 8) {
        float* row = s + g * NSEQ;
        float mx = -1e30f;
        for (int k = lane; k < NSEQ; k += 32) mx = fmaxf(mx, row[k]);
#pragma unroll
        for (int off = 16; off > 0; off >>= 1) mx = fmaxf(mx, __shfl_xor_sync(0xffffffffu, mx, off));
        float sum = 0.f;
        for (int k = lane; k < NSEQ; k += 32) {
            float e = __expf(row[k] - mx);
            row[k] = e;
            sum += e;
        }
#pragma unroll
        for (int off = 16; off > 0; off >>= 1) sum += __shfl_xor_sync(0xffffffffu, sum, off);
        const float inv = 1.f / sum;
        for (int k = lane; k < NSEQ; k += 32) row[k] *= inv;
    }
    __syncthreads();

    // mix2 column-wise, write back to g_S (each (b,q) slice touched by this block only)
    for (int k = tid; k < NSEQ; k += 256) {
        float pv[NH];
#pragma unroll
        for (int h = 0; h < NH; h++) pv[h] = s[h * NSEQ + k];
#pragma unroll
        for (int g = 0; g < NH; g++) {
            float t = bws[g];
#pragma unroll
            for (int h = 0; h < NH; h++) t += wws[g * NH + h] * pv[h];
            g_S[rowbase + (size_t)g * NSEQ * NSEQ + k] = t;
        }
    }
}

// ---------------- K4: O = P @ V per (b,h); 64 q-rows x 48 cols, k-tile 32 ----
__global__ __launch_bounds__(256) void pv_kernel() {
    __shared__ float Ps[64][33];
    __shared__ float Vs[32][HD + 1];
    const int bh = blockIdx.z;
    const int tid = threadIdx.x;
    const int qbase = blockIdx.x * 64;
    const float* Pg = g_S + (size_t)bh * NSEQ * NSEQ + (size_t)qbase * NSEQ;
    const float* Vg = g_v + (size_t)bh * NSEQ * HD;

    const int tx = tid & 15, ty = tid >> 4;
    float acc[4][3];
#pragma unroll
    for (int i = 0; i < 4; i++)
#pragma unroll
        for (int j = 0; j < 3; j++) acc[i][j] = 0.f;

    for (int kt = 0; kt < NSEQ; kt += 32) {
        for (int i = tid; i < 64 * 32; i += 256) {
            const int r = i >> 5, c = i & 31;
            Ps[r][c] = Pg[(size_t)r * NSEQ + kt + c];
        }
        for (int i = tid; i < 32 * HD; i += 256) {
            const int r = i / HD, c = i % HD;
            Vs[r][c] = Vg[(size_t)(kt + r) * HD + c];
        }
        __syncthreads();
#pragma unroll 8
        for (int kk = 0; kk < 32; kk++) {
            float p[4], vv[3];
#pragma unroll
            for (int i = 0; i < 4; i++) p[i] = Ps[ty * 4 + i][kk];
#pragma unroll
            for (int j = 0; j < 3; j++) vv[j] = Vs[kk][tx * 3 + j];
#pragma unroll
            for (int i = 0; i < 4; i++)
#pragma unroll
                for (int j = 0; j < 3; j++) acc[i][j] += p[i] * vv[j];
        }
        __syncthreads();
    }
    const int b = bh >> 4, h = bh & 15;
#pragma unroll
    for (int i = 0; i < 4; i++)
#pragma unroll
        for (int j = 0; j < 3; j++)
            g_O[(size_t)(b * NSEQ + qbase + ty * 4 + i) * DIM + h * HD + tx * 3 + j] = acc[i][j];
}

// ---------------- launch ------------------------------------------------------
extern "C" void kernel_launch(void* const* d_in, const int* in_sizes, int n_in,
                              void* d_out, int out_size) {
    const float* x      = (const float*)d_in[0];
    const float* w_qkv  = (const float*)d_in[1];
    const float* b_qkv  = (const float*)d_in[2];
    const float* w_l    = (const float*)d_in[3];
    const float* b_l    = (const float*)d_in[4];
    const float* w_w    = (const float*)d_in[5];
    const float* b_w    = (const float*)d_in[6];
    const float* w_proj = (const float*)d_in[7];
    const float* b_proj = (const float*)d_in[8];
    float* out = (float*)d_out;

    cudaFuncSetAttribute(mix_softmax_kernel,
                         cudaFuncAttributeMaxDynamicSharedMemorySize, 16 * NSEQ * 4);

    // K1: QKV projection -> g_q (scaled), g_k, g_v
    gemm128<0><<<dim3(3 * DIM / 128, BATCH * NSEQ / 128), 256>>>(x, w_qkv, b_qkv, nullptr, DIM, 3 * DIM);
    // K2: logits
    qk_kernel<<<dim3(NSEQ / 64, NSEQ / 64, BATCH * NH), 256>>>();
    // K3: mix1 + softmax + mix2 (in place on g_S)
    mix_softmax_kernel<<<BATCH * NSEQ, 256, 16 * NSEQ * 4>>>(w_l, b_l, w_w, b_w);
    // K4: P @ V -> g_O
    pv_kernel<<<dim3(NSEQ / 64, 1, BATCH * NH), 256>>>();
    // K5: output projection
    gemm128<1><<<dim3(DIM / 128, BATCH * NSEQ / 128), 256>>>(nullptr, w_proj, b_proj, out, DIM, DIM);
}

// round 2
// speedup vs baseline: 1.4277x; 1.4277x over previous
#include <cuda_runtime.h>
#include <cstdint>

#define BATCH 8
#define NSEQ 1024
#define DIM 768
#define NH 16
#define HD 48
#define SCALE 0.14433756729740643f  /* 48^-0.5 */

// ---------------- scratch (static __device__, allocation-guard safe) ----------
__device__ __align__(256) float g_q[BATCH * NH * NSEQ * HD];   // [b][h][n][d], pre-scaled
__device__ __align__(256) float g_k[BATCH * NH * NSEQ * HD];
__device__ __align__(256) float g_v[BATCH * NH * NSEQ * HD];
__device__ __align__(256) float g_S[(size_t)BATCH * NH * NSEQ * NSEQ];  // logits -> probs (in place)
__device__ __align__(256) float g_O[BATCH * NSEQ * DIM];       // attn out pre-proj

// ---------------- tf32 mma helpers -------------------------------------------
__device__ __forceinline__ uint32_t f2tf(float x) {
    uint32_t r;
    asm("cvt.rna.tf32.f32 %0, %1;" : "=r"(r) : "f"(x));
    return r;
}
__device__ __forceinline__ void mma8(float* c, const uint32_t* a, const uint32_t* b) {
    asm volatile(
        "mma.sync.aligned.m16n8k8.row.col.f32.tf32.tf32.f32 "
        "{%0,%1,%2,%3},{%4,%5,%6,%7},{%8,%9},{%0,%1,%2,%3};"
        : "+f"(c[0]), "+f"(c[1]), "+f"(c[2]), "+f"(c[3])
        : "r"(a[0]), "r"(a[1]), "r"(a[2]), "r"(a[3]), "r"(b[0]), "r"(b[1]));
}

// ---------------- generic tf32 GEMM: C = A @ W^T (+bias) ----------------------
// Block tile 128x128, K-tile 16, 8 warps (2M x 4N), warp tile 64x32.
// A: [z][M,K] row-major, W: [z][N,K] row-major. K % 16 == 0.
// MODE 0: qkv scatter epilogue. MODE 1: plain C+bias. MODE 2: batched store to g_S.
template <int MODE>
__global__ __launch_bounds__(256) void mm_tf32(
    const float* __restrict__ A, const float* __restrict__ W,
    const float* __restrict__ bias, float* __restrict__ C,
    int K, int Nc, size_t sA, size_t sW) {
    __shared__ uint32_t As[128][20];   // stride 20: (20g+t)%32 all-distinct -> conflict-free
    __shared__ uint32_t Ws[128][20];

    const int tid = threadIdx.x;
    const int m0 = blockIdx.y * 128;
    const int n0 = blockIdx.x * 128;
    const int bz = blockIdx.z;

    const float* Ag = A + (size_t)bz * sA;
    const float* Wg = W + (size_t)bz * sW;

    const int warp = tid >> 5, lane = tid & 31;
    const int wm = warp >> 2, wn = warp & 3;       // 2 x 4 warps
    const int g = lane >> 2, t = lane & 3;

    float acc[4][4][4];                            // [mt][nt][4]
#pragma unroll
    for (int i = 0; i < 4; i++)
#pragma unroll
        for (int j = 0; j < 4; j++)
#pragma unroll
            for (int e = 0; e < 4; e++) acc[i][j][e] = 0.f;

    for (int kt = 0; kt < K; kt += 16) {
#pragma unroll
        for (int i = tid; i < 512; i += 256) {
            const int r = i >> 2, c = (i & 3) * 4;
            float4 av = *(const float4*)(Ag + (size_t)(m0 + r) * K + kt + c);
            float4 wv = *(const float4*)(Wg + (size_t)(n0 + r) * K + kt + c);
            As[r][c + 0] = f2tf(av.x); As[r][c + 1] = f2tf(av.y);
            As[r][c + 2] = f2tf(av.z); As[r][c + 3] = f2tf(av.w);
            Ws[r][c + 0] = f2tf(wv.x); Ws[r][c + 1] = f2tf(wv.y);
            Ws[r][c + 2] = f2tf(wv.z); Ws[r][c + 3] = f2tf(wv.w);
        }
        __syncthreads();
#pragma unroll
        for (int ks = 0; ks < 16; ks += 8) {
            uint32_t af[4][4], bf[4][2];
#pragma unroll
            for (int mt = 0; mt < 4; mt++) {
                const int r = wm * 64 + mt * 16 + g;
                af[mt][0] = As[r][ks + t];
                af[mt][1] = As[r + 8][ks + t];
                af[mt][2] = As[r][ks + t + 4];
                af[mt][3] = As[r + 8][ks + t + 4];
            }
#pragma unroll
            for (int nt = 0; nt < 4; nt++) {
                const int n = wn * 32 + nt * 8 + g;
                bf[nt][0] = Ws[n][ks + t];
                bf[nt][1] = Ws[n][ks + t + 4];
            }
#pragma unroll
            for (int mt = 0; mt < 4; mt++)
#pragma unroll
                for (int nt = 0; nt < 4; nt++) mma8(acc[mt][nt], af[mt], bf[nt]);
        }
        __syncthreads();
    }

#pragma unroll
    for (int mt = 0; mt < 4; mt++) {
#pragma unroll
        for (int nt = 0; nt < 4; nt++) {
#pragma unroll
            for (int half = 0; half < 2; half++) {
                const int m = m0 + wm * 64 + mt * 16 + g + half * 8;
                const int c = n0 + wn * 32 + nt * 8 + 2 * t;
                const float v0 = acc[mt][nt][half * 2 + 0];
                const float v1 = acc[mt][nt][half * 2 + 1];
                if (MODE == 0) {
#pragma unroll
                    for (int e = 0; e < 2; e++) {
                        const int cc = c + e;
                        float v = (e ? v1 : v0) + bias[cc];
                        const int b = m >> 10, n = m & 1023;
                        const int tt = cc / DIM;
                        const int rr = cc - tt * DIM;
                        const int h = rr / HD, d = rr - h * HD;
                        const int idx = (((b * NH + h) * NSEQ) + n) * HD + d;
                        if (tt == 0)      g_q[idx] = v * SCALE;
                        else if (tt == 1) g_k[idx] = v;
                        else              g_v[idx] = v;
                    }
                } else if (MODE == 1) {
                    float2 o = make_float2(v0 + bias[c], v1 + bias[c + 1]);
                    *(float2*)(C + (size_t)m * Nc + c) = o;
                } else {
                    float* Cb = g_S + (size_t)bz * NSEQ * NSEQ;
                    *(float2*)(Cb + (size_t)m * NSEQ + c) = make_float2(v0, v1);
                }
            }
        }
    }
}

// ---------------- K3: fused mix1 -> softmax -> mix2, in place on g_S ---------
__global__ __launch_bounds__(256) void mix_softmax_kernel(
    const float* __restrict__ wl, const float* __restrict__ bl,
    const float* __restrict__ ww, const float* __restrict__ bw) {
    extern __shared__ float s[];  // [16][1024]
    __shared__ float wls[256], wws[256], bls[16], bws[16];

    const int tid = threadIdx.x;
    const int bq = blockIdx.x;
    const int b = bq >> 10, q = bq & 1023;

    wls[tid] = wl[tid];
    wws[tid] = ww[tid];
    if (tid < 16) { bls[tid] = bl[tid]; bws[tid] = bw[tid]; }

    const size_t rowbase = (size_t)(b * NH) * NSEQ * NSEQ + (size_t)q * NSEQ;
#pragma unroll
    for (int h = 0; h < NH; h++) {
        const float* src = g_S + rowbase + (size_t)h * NSEQ * NSEQ;
        for (int k = tid; k < NSEQ; k += 256) s[h * NSEQ + k] = src[k];
    }
    __syncthreads();

    for (int k = tid; k < NSEQ; k += 256) {
        float sv[NH], mv[NH];
#pragma unroll
        for (int h = 0; h < NH; h++) sv[h] = s[h * NSEQ + k];
#pragma unroll
        for (int gg = 0; gg < NH; gg++) {
            float tt = bls[gg];
#pragma unroll
            for (int h = 0; h < NH; h++) tt += wls[gg * NH + h] * sv[h];
            mv[gg] = tt;
        }
#pragma unroll
        for (int gg = 0; gg < NH; gg++) s[gg * NSEQ + k] = mv[gg];
    }
    __syncthreads();

    const int lane = tid & 31, warp = tid >> 5;
    for (int gg = warp; gg < NH; gg += 8) {
        float* row = s + gg * NSEQ;
        float mx = -1e30f;
        for (int k = lane; k < NSEQ; k += 32) mx = fmaxf(mx, row[k]);
#pragma unroll
        for (int off = 16; off > 0; off >>= 1) mx = fmaxf(mx, __shfl_xor_sync(0xffffffffu, mx, off));
        float sum = 0.f;
        for (int k = lane; k < NSEQ; k += 32) {
            float e = __expf(row[k] - mx);
            row[k] = e;
            sum += e;
        }
#pragma unroll
        for (int off = 16; off > 0; off >>= 1) sum += __shfl_xor_sync(0xffffffffu, sum, off);
        const float inv = 1.f / sum;
        for (int k = lane; k < NSEQ; k += 32) row[k] *= inv;
    }
    __syncthreads();

    for (int k = tid; k < NSEQ; k += 256) {
        float pv[NH];
#pragma unroll
        for (int h = 0; h < NH; h++) pv[h] = s[h * NSEQ + k];
#pragma unroll
        for (int gg = 0; gg < NH; gg++) {
            float tt = bws[gg];
#pragma unroll
            for (int h = 0; h < NH; h++) tt += wws[gg * NH + h] * pv[h];
            g_S[rowbase + (size_t)gg * NSEQ * NSEQ + k] = tt;
        }
    }
}

// ---------------- K4: O = P @ V per (b,h), tf32 mma --------------------------
// Block 128 q-rows x 48 cols. 8 warps (4M x 2N), warp tile 32x24 (2 mt x 3 nt).
__global__ __launch_bounds__(256) void pv_tf32() {
    __shared__ uint32_t Ps[128][36];   // stride 36: (4g+t)%32 distinct -> conflict-free
    __shared__ uint32_t Vs[HD][36];    // V transposed: Vs[d][k]

    const int bh = blockIdx.z;
    const int tid = threadIdx.x;
    const int qbase = blockIdx.x * 128;
    const float* Pg = g_S + (size_t)bh * NSEQ * NSEQ + (size_t)qbase * NSEQ;
    const float* Vg = g_v + (size_t)bh * NSEQ * HD;

    const int warp = tid >> 5, lane = tid & 31;
    const int wm = warp >> 1, wn = warp & 1;       // 4 x 2 warps
    const int g = lane >> 2, t = lane & 3;

    float acc[2][3][4];
#pragma unroll
    for (int i = 0; i < 2; i++)
#pragma unroll
        for (int j = 0; j < 3; j++)
#pragma unroll
            for (int e = 0; e < 4; e++) acc[i][j][e] = 0.f;

    for (int kt = 0; kt < NSEQ; kt += 32) {
#pragma unroll
        for (int i = tid; i < 1024; i += 256) {   // P tile 128x32
            const int r = i >> 3, c = (i & 7) * 4;
            float4 v = *(const float4*)(Pg + (size_t)r * NSEQ + kt + c);
            Ps[r][c + 0] = f2tf(v.x); Ps[r][c + 1] = f2tf(v.y);
            Ps[r][c + 2] = f2tf(v.z); Ps[r][c + 3] = f2tf(v.w);
        }
#pragma unroll
        for (int i = tid; i < 32 * HD; i += 256) {  // V tile 32x48 -> transpose
            const int k = i & 31, d = i >> 5;
            Vs[d][k] = f2tf(Vg[(size_t)(kt + k) * HD + d]);
        }
        __syncthreads();
#pragma unroll
        for (int ks = 0; ks < 32; ks += 8) {
            uint32_t af[2][4], bf[3][2];
#pragma unroll
            for (int mt = 0; mt < 2; mt++) {
                const int r = wm * 32 + mt * 16 + g;
                af[mt][0] = Ps[r][ks + t];
                af[mt][1] = Ps[r + 8][ks + t];
                af[mt][2] = Ps[r][ks + t + 4];
                af[mt][3] = Ps[r + 8][ks + t + 4];
            }
#pragma unroll
            for (int nt = 0; nt < 3; nt++) {
                const int n = wn * 24 + nt * 8 + g;
                bf[nt][0] = Vs[n][ks + t];
                bf[nt][1] = Vs[n][ks + t + 4];
            }
#pragma unroll
            for (int mt = 0; mt < 2; mt++)
#pragma unroll
                for (int nt = 0; nt < 3; nt++) mma8(acc[mt][nt], af[mt], bf[nt]);
        }
        __syncthreads();
    }

    const int b = bh >> 4, h = bh & 15;
#pragma unroll
    for (int mt = 0; mt < 2; mt++)
#pragma unroll
        for (int nt = 0; nt < 3; nt++)
#pragma unroll
            for (int half = 0; half < 2; half++) {
                const int q = qbase + wm * 32 + mt * 16 + g + half * 8;
                const int d = wn * 24 + nt * 8 + 2 * t;
                float2 o = make_float2(acc[mt][nt][half * 2], acc[mt][nt][half * 2 + 1]);
                *(float2*)(g_O + (size_t)(b * NSEQ + q) * DIM + h * HD + d) = o;
            }
}

// ---------------- launch ------------------------------------------------------
extern "C" void kernel_launch(void* const* d_in, const int* in_sizes, int n_in,
                              void* d_out, int out_size) {
    const float* x      = (const float*)d_in[0];
    const float* w_qkv  = (const float*)d_in[1];
    const float* b_qkv  = (const float*)d_in[2];
    const float* w_l    = (const float*)d_in[3];
    const float* b_l    = (const float*)d_in[4];
    const float* w_w    = (const float*)d_in[5];
    const float* b_w    = (const float*)d_in[6];
    const float* w_proj = (const float*)d_in[7];
    const float* b_proj = (const float*)d_in[8];
    float* out = (float*)d_out;

    cudaFuncSetAttribute(mix_softmax_kernel,
                         cudaFuncAttributeMaxDynamicSharedMemorySize, 16 * NSEQ * 4);

    float* gq_p; cudaGetSymbolAddress((void**)&gq_p, g_q);
    float* gk_p; cudaGetSymbolAddress((void**)&gk_p, g_k);
    float* gO_p; cudaGetSymbolAddress((void**)&gO_p, g_O);

    // K1: QKV projection -> g_q (scaled), g_k, g_v   [M=8192, N=2304, K=768]
    mm_tf32<0><<<dim3(3 * DIM / 128, BATCH * NSEQ / 128, 1), 256>>>(
        x, w_qkv, b_qkv, nullptr, DIM, 3 * DIM, 0, 0);
    // K2: logits  S = q @ k^T  per (b,h)   [z=128, M=N=1024, K=48]
    mm_tf32<2><<<dim3(NSEQ / 128, NSEQ / 128, BATCH * NH), 256>>>(
        gq_p, gk_p, nullptr, nullptr, HD, NSEQ,
        (size_t)NSEQ * HD, (size_t)NSEQ * HD);
    // K3: mix1 + softmax + mix2 (in place on g_S)
    mix_softmax_kernel<<<BATCH * NSEQ, 256, 16 * NSEQ * 4>>>(w_l, b_l, w_w, b_w);
    // K4: P @ V -> g_O
    pv_tf32<<<dim3(NSEQ / 128, 1, BATCH * NH), 256>>>();
    // K5: output projection  [M=8192, N=768, K=768]
    mm_tf32<1><<<dim3(DIM / 128, BATCH * NSEQ / 128, 1), 256>>>(
        gO_p, w_proj, b_proj, out, DIM, DIM, 0, 0);
}